// round 13
// baseline (speedup 1.0000x reference)
#include <cuda_runtime.h>
#include <cuda_bf16.h>
#include <cstdint>

// Problem constants  (B,T,D,H,L,F = 128,512,32,128,3,4)
#define BATCH 128
#define TT    512
#define DIN   32
#define HID   128
#define GATES 512   // 4*HID
#define FOUT  4

typedef unsigned long long ull;

// ---------------------------------------------------------------------------
// Device scratch
// ---------------------------------------------------------------------------
__device__ float g_pre[BATCH * TT * GATES];
__device__ float g_hs0[BATCH * TT * HID];
__device__ float g_hs1[BATCH * TT * HID];
__device__ float g_ctx[BATCH * HID];

// ---------------------------------------------------------------------------
// Packed f32x2 helpers (sm_100+)
// ---------------------------------------------------------------------------
__device__ __forceinline__ ull pack2(float lo, float hi) {
    ull r;
    asm("mov.b64 %0, {%1, %2};" : "=l"(r) : "f"(lo), "f"(hi));
    return r;
}
__device__ __forceinline__ void unpack2(ull v, float& lo, float& hi) {
    asm("mov.b64 {%0, %1}, %2;" : "=f"(lo), "=f"(hi) : "l"(v));
}
__device__ __forceinline__ void ffma2(ull& d, ull a, ull b) {
    asm("fma.rn.f32x2 %0, %1, %2, %0;" : "+l"(d) : "l"(a), "l"(b));
}

// fast activations (MUFU-based) — verified R7 (rel 2.5e-4)
__device__ __forceinline__ float fast_sigmoid(float x) {
    return __fdividef(1.f, 1.f + __expf(-x));
}
__device__ __forceinline__ float fast_tanh(float x) {
    float e = __expf(2.f * x);            // inf-safe
    return 1.f - __fdividef(2.f, e + 1.f);
}

// ---------------------------------------------------------------------------
// GEMM (FFMA2, double-buffered — measured best; ~85% of FFMA2 roofline)
// ---------------------------------------------------------------------------
#define GBM 128
#define GBN 128
#define GBK 16

__global__ void __launch_bounds__(256) gemm_bias_kernel(
    const float* __restrict__ A,
    const float* __restrict__ W,
    const float* __restrict__ bi,
    const float* __restrict__ bh,
    float* __restrict__ out,
    int K)
{
    __shared__ float As[2][GBK][GBM];
    __shared__ float Ws[2][GBK][GBN];

    const int bm = blockIdx.x;
    const int bn = blockIdx.y;
    const int tid = threadIdx.x;
    const int tx = tid & 15;
    const int ty = tid >> 4;

    const int lrow = tid >> 1;
    const int lq   = (tid & 1) * 2;

    const float* Ab = A + (size_t)(bm * GBM) * K;
    const float* Wb = W + (size_t)(bn * GBN) * K;

    ull acc[8][4];
    {
#pragma unroll
        for (int j = 0; j < 4; j++) {
            int n = bn * GBN + 2 * tx + 32 * j;
            ull bp = pack2(__ldg(&bi[n]) + __ldg(&bh[n]),
                           __ldg(&bi[n + 1]) + __ldg(&bh[n + 1]));
#pragma unroll
            for (int i = 0; i < 8; i++) acc[i][j] = bp;
        }
    }

    const int nb = K / GBK;

    float4 avr[2], wvr[2];
#pragma unroll
    for (int h = 0; h < 2; h++) {
        int kb = (lq + h) * 4;
        avr[h] = *(const float4*)(Ab + (size_t)lrow * K + kb);
        wvr[h] = *(const float4*)(Wb + (size_t)lrow * K + kb);
    }
#pragma unroll
    for (int h = 0; h < 2; h++) {
        int kb = (lq + h) * 4;
        As[0][kb + 0][lrow] = avr[h].x; As[0][kb + 1][lrow] = avr[h].y;
        As[0][kb + 2][lrow] = avr[h].z; As[0][kb + 3][lrow] = avr[h].w;
        Ws[0][kb + 0][lrow] = wvr[h].x; Ws[0][kb + 1][lrow] = wvr[h].y;
        Ws[0][kb + 2][lrow] = wvr[h].z; Ws[0][kb + 3][lrow] = wvr[h].w;
    }
    __syncthreads();

    for (int it = 0; it < nb; it++) {
        const int cur = it & 1;
        const bool has_next = (it + 1 < nb);

        if (has_next) {
            int k0 = (it + 1) * GBK;
#pragma unroll
            for (int h = 0; h < 2; h++) {
                int kb = (lq + h) * 4;
                avr[h] = *(const float4*)(Ab + (size_t)lrow * K + k0 + kb);
                wvr[h] = *(const float4*)(Wb + (size_t)lrow * K + k0 + kb);
            }
        }

#pragma unroll
        for (int k = 0; k < GBK; k++) {
            const ull* wrow = (const ull*)&Ws[cur][k][0];
            ull w0 = wrow[tx];
            ull w1 = wrow[tx + 16];
            ull w2 = wrow[tx + 32];
            ull w3 = wrow[tx + 48];
            float4 a0 = *(const float4*)&As[cur][k][ty * 8];
            float4 a1 = *(const float4*)&As[cur][k][ty * 8 + 4];
            ull ap[8];
            ap[0] = pack2(a0.x, a0.x); ap[1] = pack2(a0.y, a0.y);
            ap[2] = pack2(a0.z, a0.z); ap[3] = pack2(a0.w, a0.w);
            ap[4] = pack2(a1.x, a1.x); ap[5] = pack2(a1.y, a1.y);
            ap[6] = pack2(a1.z, a1.z); ap[7] = pack2(a1.w, a1.w);
#pragma unroll
            for (int i = 0; i < 8; i++) {
                ffma2(acc[i][0], ap[i], w0);
                ffma2(acc[i][1], ap[i], w1);
                ffma2(acc[i][2], ap[i], w2);
                ffma2(acc[i][3], ap[i], w3);
            }
        }

        if (has_next) {
            const int alt = cur ^ 1;
#pragma unroll
            for (int h = 0; h < 2; h++) {
                int kb = (lq + h) * 4;
                As[alt][kb + 0][lrow] = avr[h].x; As[alt][kb + 1][lrow] = avr[h].y;
                As[alt][kb + 2][lrow] = avr[h].z; As[alt][kb + 3][lrow] = avr[h].w;
                Ws[alt][kb + 0][lrow] = wvr[h].x; Ws[alt][kb + 1][lrow] = wvr[h].y;
                Ws[alt][kb + 2][lrow] = wvr[h].z; Ws[alt][kb + 3][lrow] = wvr[h].w;
            }
            __syncthreads();
        }
    }

    const int m0 = bm * GBM + ty * 8;
#pragma unroll
    for (int i = 0; i < 8; i++) {
#pragma unroll
        for (int j = 0; j < 4; j++) {
            float lo, hi;
            unpack2(acc[i][j], lo, hi);
            int n = bn * GBN + 2 * tx + 32 * j;
            *(float2*)&out[(size_t)(m0 + i) * GATES + n] = make_float2(lo, hi);
        }
    }
}

// ---------------------------------------------------------------------------
// LSTM — R12 base with ONE change: gate activations applied by the OWNING
// thread BEFORE the gbuf exchange (row tid: sigmoid; row 256+tid: tanh for
// tid<128 (g), sigmoid for tid>=128 (o) — warp-uniform). Serial tail shrinks
// to c-update + one tanh. Bitwise-identical values, different thread.
// ---------------------------------------------------------------------------
#define WSU_PAIRS 32
#define LSTM_SMEM_FLOATS (WSU_PAIRS * 256 * 2 + GATES + HID)

__global__ void __launch_bounds__(256, 1) lstm_kernel(
    const float* __restrict__ pre,   // [B][T][512]
    const float* __restrict__ whh,   // [512][128]
    float* __restrict__ hs)          // [B][T][128]
{
    extern __shared__ float smem[];
    ull*   wsu  = (ull*)smem;                         // [32][256] k-pairs 32..63 of row tid
    float* gbuf = smem + WSU_PAIRS * 256 * 2;         // [512] (activated gates)
    float* hvec = gbuf + GATES;                       // [128], 16B aligned

    const int b = blockIdx.x;
    const int tid = threadIdx.x;

    // register weights
    ull wr[64];     // row 256+tid, all 64 k-pairs
    ull ws_lo[32];  // row tid, k-pairs 0..31
    {
        const float4* r4 = (const float4*)(whh + (size_t)(256 + tid) * HID);
#pragma unroll
        for (int i = 0; i < 32; i++) {
            float4 v = r4[i];
            wr[2 * i]     = pack2(v.x, v.y);
            wr[2 * i + 1] = pack2(v.z, v.w);
        }
        const float4* s4 = (const float4*)(whh + (size_t)tid * HID);
#pragma unroll
        for (int i = 0; i < 16; i++) {
            float4 v = s4[i];
            ws_lo[2 * i]     = pack2(v.x, v.y);
            ws_lo[2 * i + 1] = pack2(v.z, v.w);
        }
        // smem half: row tid, k-pairs 32..63 (scalar ull layout)
#pragma unroll
        for (int i = 0; i < 16; i++) {
            float4 v = s4[16 + i];
            wsu[(2 * i) * 256 + tid]     = pack2(v.x, v.y);
            wsu[(2 * i + 1) * 256 + tid] = pack2(v.z, v.w);
        }
    }
    if (tid < HID) hvec[tid] = 0.f;
    float c = 0.f;
    __syncthreads();

    const float* preb = pre + (size_t)b * TT * GATES;
    float* hsb = hs + (size_t)b * TT * HID;

    float p_lo = preb[tid];
    float p_hi = preb[256 + tid];

#pragma unroll 1
    for (int t = 0; t < TT; t++) {
        ull ar0 = 0, ar1 = 0, as0 = 0, as1 = 0;

        if (t + 1 < TT) {
            const float* pn = preb + (size_t)(t + 1) * GATES;
            p_lo = pn[tid];
            p_hi = pn[256 + tid];
        }

        const ulonglong2* hu4 = (const ulonglong2*)hvec;
#pragma unroll
        for (int i = 0; i < 16; i++) {
            ull w0 = wsu[(2 * i) * 256 + tid];      // row tid, pair 32+2i
            ull w1 = wsu[(2 * i + 1) * 256 + tid];  // row tid, pair 33+2i
            ulonglong2 ha = hu4[i];                 // h pairs 2i, 2i+1 (16B bcast)
            ulonglong2 hb = hu4[16 + i];            // h pairs 32+2i, 33+2i
            ffma2(ar0, wr[2 * i],      ha.x);
            ffma2(ar1, wr[32 + 2 * i], hb.x);
            ffma2(as0, ws_lo[2 * i],   ha.x);
            ffma2(as1, w0,             hb.x);
            ffma2(ar0, wr[2 * i + 1],  ha.y);
            ffma2(ar1, wr[33 + 2 * i], hb.y);
            ffma2(as0, ws_lo[2 * i + 1], ha.y);
            ffma2(as1, w1,             hb.y);
        }

        float r0l, r0h, r1l, r1h, s0l, s0h, s1l, s1h;
        unpack2(ar0, r0l, r0h);
        unpack2(ar1, r1l, r1h);
        unpack2(as0, s0l, s0h);
        unpack2(as1, s1l, s1h);
        float acc_r = p_hi + ((r0l + r0h) + (r1l + r1h));
        float acc_s = p_lo + ((s0l + s0h) + (s1l + s1h));

        // Apply activations HERE (owning thread), before the exchange.
        // Row tid (0..255) is i (tid<128) or f (tid>=128): sigmoid either way.
        // Row 256+tid is g (tid<128, tanh) or o (tid>=128, sigmoid).
        float act_s = fast_sigmoid(acc_s);
        float act_r = (tid < 128) ? fast_tanh(acc_r) : fast_sigmoid(acc_r);

        gbuf[tid]       = act_s;
        gbuf[256 + tid] = act_r;
        __syncthreads();

        if (tid < HID) {
            float iv = gbuf[tid];            // sigmoid(i)
            float fv = gbuf[128 + tid];      // sigmoid(f)
            float gv = gbuf[256 + tid];      // tanh(g)
            float ov = gbuf[384 + tid];      // sigmoid(o)
            c = fmaf(fv, c, iv * gv);
            float h = ov * fast_tanh(c);
            hvec[tid] = h;
            hsb[(size_t)t * HID + tid] = h;
        }
        __syncthreads();
    }
}

// ---------------------------------------------------------------------------
// Attention pooling (unchanged, verified)
// ---------------------------------------------------------------------------
__global__ void __launch_bounds__(128) attn_kernel(
    const float* __restrict__ hs,
    const float* __restrict__ w_attn,
    const float* __restrict__ b_attn,
    float* __restrict__ ctx)
{
    __shared__ float wv[HID];
    __shared__ float lg[TT];
    __shared__ float red[4];

    const int b = blockIdx.x;
    const int tid = threadIdx.x;

    wv[tid] = w_attn[tid];
    __syncthreads();

    const float* hb = hs + (size_t)b * TT * HID;
    const float battn = __ldg(&b_attn[0]);

    for (int t = tid; t < TT; t += 128) {
        const float4* row = (const float4*)(hb + (size_t)t * HID);
        const float4* wr4 = (const float4*)wv;
        float s = 0.f;
#pragma unroll
        for (int k = 0; k < HID / 4; k++) {
            float4 v = row[k];
            float4 w = wr4[k];
            s = fmaf(v.x, w.x, s);
            s = fmaf(v.y, w.y, s);
            s = fmaf(v.z, w.z, s);
            s = fmaf(v.w, w.w, s);
        }
        lg[t] = s + battn;
    }
    __syncthreads();

    float m = -1e30f;
    for (int t = tid; t < TT; t += 128) m = fmaxf(m, lg[t]);
#pragma unroll
    for (int o = 16; o > 0; o >>= 1) m = fmaxf(m, __shfl_xor_sync(0xffffffffu, m, o));
    if ((tid & 31) == 0) red[tid >> 5] = m;
    __syncthreads();
    m = fmaxf(fmaxf(red[0], red[1]), fmaxf(red[2], red[3]));
    __syncthreads();

    float z = 0.f;
    for (int t = tid; t < TT; t += 128) {
        float e = __expf(lg[t] - m);
        lg[t] = e;
        z += e;
    }
#pragma unroll
    for (int o = 16; o > 0; o >>= 1) z += __shfl_xor_sync(0xffffffffu, z, o);
    __syncthreads();
    if ((tid & 31) == 0) red[tid >> 5] = z;
    __syncthreads();
    z = red[0] + red[1] + red[2] + red[3];
    const float inv = 1.f / z;

    float acc = 0.f;
    for (int t = 0; t < TT; t++)
        acc = fmaf(lg[t], hb[(size_t)t * HID + tid], acc);
    ctx[(size_t)b * HID + tid] = acc * inv;
}

// ---------------------------------------------------------------------------
// MLP head (unchanged, verified)
// ---------------------------------------------------------------------------
__global__ void __launch_bounds__(128) mlp_kernel(
    const float* __restrict__ ctx,
    const float* __restrict__ w1, const float* __restrict__ b1,
    const float* __restrict__ w2, const float* __restrict__ b2,
    float* __restrict__ out)
{
    __shared__ float cs[HID];
    __shared__ float h1[64];

    const int b = blockIdx.x;
    const int tid = threadIdx.x;

    cs[tid] = ctx[(size_t)b * HID + tid];
    __syncthreads();

    if (tid < 64) {
        const float* wr = w1 + (size_t)tid * HID;
        float s = __ldg(&b1[tid]);
#pragma unroll 8
        for (int k = 0; k < HID; k++) s = fmaf(wr[k], cs[k], s);
        h1[tid] = fmaxf(s, 0.f);
    }
    __syncthreads();

    if (tid < FOUT) {
        const float* wr = w2 + (size_t)tid * 64;
        float s = __ldg(&b2[tid]);
#pragma unroll 8
        for (int k = 0; k < 64; k++) s = fmaf(wr[k], h1[k], s);
        out[(size_t)b * FOUT + tid] = s;
    }
}

// ---------------------------------------------------------------------------
// kernel_launch — wiring identical to R5-R12 (verified passing).
// ---------------------------------------------------------------------------
extern "C" void kernel_launch(void* const* d_in, const int* in_sizes, int n_in,
                              void* d_out, int out_size)
{
    const float *x = 0, *w_ih0 = 0, *w_ihr = 0, *w_hh = 0;
    const float *b_ih = 0, *b_hh = 0, *w_attn = 0, *b_attn = 0;
    const float *w1 = 0, *b1 = 0, *w2 = 0, *b2 = 0;

    int unit_bytes = 0, unit_elems = 0;
    for (int i = 0; i < n_in; i++) {
        if (in_sizes[i] == 8388608) unit_bytes = 1;
        if (in_sizes[i] == 2097152) unit_elems = 1;
    }

    if (unit_bytes || unit_elems) {
        const int div = unit_bytes ? 4 : 1;
        for (int i = 0; i < n_in; i++) {
            const float* p = (const float*)d_in[i];
            long long e = (long long)in_sizes[i] / div;
            switch (e) {
                case 2097152: x      = p; break;
                case 196608:  w_hh   = p; break;
                case 131072:  w_ihr  = p; break;
                case 16384:   w_ih0  = p; break;
                case 8192:    w1     = p; break;
                case 1536:    if (!b_ih) b_ih = p; else b_hh = p; break;
                case 256:     w2     = p; break;
                case 128:     w_attn = p; break;
                case 64:      b1     = p; break;
                case 4:       b2     = p; break;
                case 1:       b_attn = p; break;
                default: break;
            }
        }
    }

    if (n_in >= 12) {
        if (!x)      x      = (const float*)d_in[0];
        if (!w_ih0)  w_ih0  = (const float*)d_in[1];
        if (!w_ihr)  w_ihr  = (const float*)d_in[2];
        if (!w_hh)   w_hh   = (const float*)d_in[3];
        if (!b_ih)   b_ih   = (const float*)d_in[4];
        if (!b_hh)   b_hh   = (const float*)d_in[5];
        if (!w_attn) w_attn = (const float*)d_in[6];
        if (!b_attn) b_attn = (const float*)d_in[7];
        if (!w1)     w1     = (const float*)d_in[8];
        if (!b1)     b1     = (const float*)d_in[9];
        if (!w2)     w2     = (const float*)d_in[10];
        if (!b2)     b2     = (const float*)d_in[11];
    }

    float* out = (float*)d_out;

    float *pre = nullptr, *hs0 = nullptr, *hs1 = nullptr, *ctx = nullptr;
    cudaGetSymbolAddress((void**)&pre, g_pre);
    cudaGetSymbolAddress((void**)&hs0, g_hs0);
    cudaGetSymbolAddress((void**)&hs1, g_hs1);
    cudaGetSymbolAddress((void**)&ctx, g_ctx);

    const size_t lstm_smem = LSTM_SMEM_FLOATS * sizeof(float);  // ~68 KB
    cudaFuncSetAttribute(lstm_kernel,
                         cudaFuncAttributeMaxDynamicSharedMemorySize,
                         (int)lstm_smem);

    dim3 ggrid(BATCH * TT / GBM, GATES / GBN);   // 512 x 4

    // Layer 0
    gemm_bias_kernel<<<ggrid, 256>>>(x, w_ih0, b_ih + 0 * GATES, b_hh + 0 * GATES, pre, DIN);
    lstm_kernel<<<BATCH, 256, lstm_smem>>>(pre, w_hh + (size_t)0 * GATES * HID, hs0);

    // Layer 1
    gemm_bias_kernel<<<ggrid, 256>>>(hs0, w_ihr + (size_t)0 * GATES * HID,
                                     b_ih + 1 * GATES, b_hh + 1 * GATES, pre, HID);
    lstm_kernel<<<BATCH, 256, lstm_smem>>>(pre, w_hh + (size_t)1 * GATES * HID, hs1);

    // Layer 2
    gemm_bias_kernel<<<ggrid, 256>>>(hs1, w_ihr + (size_t)1 * GATES * HID,
                                     b_ih + 2 * GATES, b_hh + 2 * GATES, pre, HID);
    lstm_kernel<<<BATCH, 256, lstm_smem>>>(pre, w_hh + (size_t)2 * GATES * HID, hs0);

    // Attention pooling + MLP head
    attn_kernel<<<BATCH, 128>>>(hs0, w_attn, b_attn, ctx);
    mlp_kernel<<<BATCH, 128>>>(ctx, w1, b1, w2, b2, out);
}

// round 14
// speedup vs baseline: 1.0297x; 1.0297x over previous
#include <cuda_runtime.h>
#include <cuda_bf16.h>
#include <cstdint>

// Problem constants  (B,T,D,H,L,F = 128,512,32,128,3,4)
#define BATCH 128
#define TT    512
#define DIN   32
#define HID   128
#define GATES 512   // 4*HID
#define FOUT  4

typedef unsigned long long ull;

// ---------------------------------------------------------------------------
// Device scratch
// ---------------------------------------------------------------------------
__device__ float g_pre[BATCH * TT * GATES];
__device__ float g_hs0[BATCH * TT * HID];
__device__ float g_hs1[BATCH * TT * HID];
__device__ float g_ctx[BATCH * HID];

// ---------------------------------------------------------------------------
// Packed f32x2 helpers (sm_100+)
// ---------------------------------------------------------------------------
__device__ __forceinline__ ull pack2(float lo, float hi) {
    ull r;
    asm("mov.b64 %0, {%1, %2};" : "=l"(r) : "f"(lo), "f"(hi));
    return r;
}
__device__ __forceinline__ void unpack2(ull v, float& lo, float& hi) {
    asm("mov.b64 {%0, %1}, %2;" : "=f"(lo), "=f"(hi) : "l"(v));
}
__device__ __forceinline__ void ffma2(ull& d, ull a, ull b) {
    asm("fma.rn.f32x2 %0, %1, %2, %0;" : "+l"(d) : "l"(a), "l"(b));
}

// fast activations (MUFU-based) — verified (rel 2.5e-4)
__device__ __forceinline__ float fast_sigmoid(float x) {
    return __fdividef(1.f, 1.f + __expf(-x));
}
__device__ __forceinline__ float fast_tanh(float x) {
    float e = __expf(2.f * x);            // inf-safe
    return 1.f - __fdividef(2.f, e + 1.f);
}

// ---------------------------------------------------------------------------
// GEMM (FFMA2, double-buffered — measured best; ~85% of FFMA2 roofline)
// ---------------------------------------------------------------------------
#define GBM 128
#define GBN 128
#define GBK 16

__global__ void __launch_bounds__(256) gemm_bias_kernel(
    const float* __restrict__ A,
    const float* __restrict__ W,
    const float* __restrict__ bi,
    const float* __restrict__ bh,
    float* __restrict__ out,
    int K)
{
    __shared__ float As[2][GBK][GBM];
    __shared__ float Ws[2][GBK][GBN];

    const int bm = blockIdx.x;
    const int bn = blockIdx.y;
    const int tid = threadIdx.x;
    const int tx = tid & 15;
    const int ty = tid >> 4;

    const int lrow = tid >> 1;
    const int lq   = (tid & 1) * 2;

    const float* Ab = A + (size_t)(bm * GBM) * K;
    const float* Wb = W + (size_t)(bn * GBN) * K;

    ull acc[8][4];
    {
#pragma unroll
        for (int j = 0; j < 4; j++) {
            int n = bn * GBN + 2 * tx + 32 * j;
            ull bp = pack2(__ldg(&bi[n]) + __ldg(&bh[n]),
                           __ldg(&bi[n + 1]) + __ldg(&bh[n + 1]));
#pragma unroll
            for (int i = 0; i < 8; i++) acc[i][j] = bp;
        }
    }

    const int nb = K / GBK;

    float4 avr[2], wvr[2];
#pragma unroll
    for (int h = 0; h < 2; h++) {
        int kb = (lq + h) * 4;
        avr[h] = *(const float4*)(Ab + (size_t)lrow * K + kb);
        wvr[h] = *(const float4*)(Wb + (size_t)lrow * K + kb);
    }
#pragma unroll
    for (int h = 0; h < 2; h++) {
        int kb = (lq + h) * 4;
        As[0][kb + 0][lrow] = avr[h].x; As[0][kb + 1][lrow] = avr[h].y;
        As[0][kb + 2][lrow] = avr[h].z; As[0][kb + 3][lrow] = avr[h].w;
        Ws[0][kb + 0][lrow] = wvr[h].x; Ws[0][kb + 1][lrow] = wvr[h].y;
        Ws[0][kb + 2][lrow] = wvr[h].z; Ws[0][kb + 3][lrow] = wvr[h].w;
    }
    __syncthreads();

    for (int it = 0; it < nb; it++) {
        const int cur = it & 1;
        const bool has_next = (it + 1 < nb);

        if (has_next) {
            int k0 = (it + 1) * GBK;
#pragma unroll
            for (int h = 0; h < 2; h++) {
                int kb = (lq + h) * 4;
                avr[h] = *(const float4*)(Ab + (size_t)lrow * K + k0 + kb);
                wvr[h] = *(const float4*)(Wb + (size_t)lrow * K + k0 + kb);
            }
        }

#pragma unroll
        for (int k = 0; k < GBK; k++) {
            const ull* wrow = (const ull*)&Ws[cur][k][0];
            ull w0 = wrow[tx];
            ull w1 = wrow[tx + 16];
            ull w2 = wrow[tx + 32];
            ull w3 = wrow[tx + 48];
            float4 a0 = *(const float4*)&As[cur][k][ty * 8];
            float4 a1 = *(const float4*)&As[cur][k][ty * 8 + 4];
            ull ap[8];
            ap[0] = pack2(a0.x, a0.x); ap[1] = pack2(a0.y, a0.y);
            ap[2] = pack2(a0.z, a0.z); ap[3] = pack2(a0.w, a0.w);
            ap[4] = pack2(a1.x, a1.x); ap[5] = pack2(a1.y, a1.y);
            ap[6] = pack2(a1.z, a1.z); ap[7] = pack2(a1.w, a1.w);
#pragma unroll
            for (int i = 0; i < 8; i++) {
                ffma2(acc[i][0], ap[i], w0);
                ffma2(acc[i][1], ap[i], w1);
                ffma2(acc[i][2], ap[i], w2);
                ffma2(acc[i][3], ap[i], w3);
            }
        }

        if (has_next) {
            const int alt = cur ^ 1;
#pragma unroll
            for (int h = 0; h < 2; h++) {
                int kb = (lq + h) * 4;
                As[alt][kb + 0][lrow] = avr[h].x; As[alt][kb + 1][lrow] = avr[h].y;
                As[alt][kb + 2][lrow] = avr[h].z; As[alt][kb + 3][lrow] = avr[h].w;
                Ws[alt][kb + 0][lrow] = wvr[h].x; Ws[alt][kb + 1][lrow] = wvr[h].y;
                Ws[alt][kb + 2][lrow] = wvr[h].z; Ws[alt][kb + 3][lrow] = wvr[h].w;
            }
            __syncthreads();
        }
    }

    const int m0 = bm * GBM + ty * 8;
#pragma unroll
    for (int i = 0; i < 8; i++) {
#pragma unroll
        for (int j = 0; j < 4; j++) {
            float lo, hi;
            unpack2(acc[i][j], lo, hi);
            int n = bn * GBN + 2 * tx + 32 * j;
            *(float2*)&out[(size_t)(m0 + i) * GATES + n] = make_float2(lo, hi);
        }
    }
}

// ---------------------------------------------------------------------------
// LSTM — R12 base with ONE change: weight split shifted to free 16 registers.
// ws_lo keeps k-pairs 0..23 in regs (24 ull); pairs 24..31 move to smem
// (wsu rows 32..39). wsu rows 0..31 still hold pairs 32..63. Same math,
// same exchange, same post-barrier activations (R11/R12 structure).
// Goal: regs 254 -> ~238 so ptxas can software-pipeline the LDS.
// ---------------------------------------------------------------------------
#define WSU_ROWS 40
#define LSTM_SMEM_FLOATS (WSU_ROWS * 256 * 2 + GATES + HID)

__global__ void __launch_bounds__(256, 1) lstm_kernel(
    const float* __restrict__ pre,   // [B][T][512]
    const float* __restrict__ whh,   // [512][128]
    float* __restrict__ hs)          // [B][T][128]
{
    extern __shared__ float smem[];
    ull*   wsu  = (ull*)smem;                         // [40][256]
    float* gbuf = smem + WSU_ROWS * 256 * 2;          // [512]
    float* hvec = gbuf + GATES;                       // [128], 16B aligned

    const int b = blockIdx.x;
    const int tid = threadIdx.x;

    // register weights
    ull wr[64];     // row 256+tid, all 64 k-pairs
    ull ws_lo[24];  // row tid, k-pairs 0..23
    {
        const float4* r4 = (const float4*)(whh + (size_t)(256 + tid) * HID);
#pragma unroll
        for (int i = 0; i < 32; i++) {
            float4 v = r4[i];
            wr[2 * i]     = pack2(v.x, v.y);
            wr[2 * i + 1] = pack2(v.z, v.w);
        }
        const float4* s4 = (const float4*)(whh + (size_t)tid * HID);
#pragma unroll
        for (int i = 0; i < 12; i++) {
            float4 v = s4[i];
            ws_lo[2 * i]     = pack2(v.x, v.y);
            ws_lo[2 * i + 1] = pack2(v.z, v.w);
        }
        // smem rows 32..39: row tid, k-pairs 24..31
#pragma unroll
        for (int i = 12; i < 16; i++) {
            float4 v = s4[i];
            wsu[(32 + 2 * (i - 12)) * 256 + tid] = pack2(v.x, v.y);
            wsu[(33 + 2 * (i - 12)) * 256 + tid] = pack2(v.z, v.w);
        }
        // smem rows 0..31: row tid, k-pairs 32..63
#pragma unroll
        for (int i = 0; i < 16; i++) {
            float4 v = s4[16 + i];
            wsu[(2 * i) * 256 + tid]     = pack2(v.x, v.y);
            wsu[(2 * i + 1) * 256 + tid] = pack2(v.z, v.w);
        }
    }
    if (tid < HID) hvec[tid] = 0.f;
    float c = 0.f;
    __syncthreads();

    const float* preb = pre + (size_t)b * TT * GATES;
    float* hsb = hs + (size_t)b * TT * HID;

    float p_lo = preb[tid];
    float p_hi = preb[256 + tid];

#pragma unroll 1
    for (int t = 0; t < TT; t++) {
        ull ar0 = 0, ar1 = 0, as0 = 0, as1 = 0;

        if (t + 1 < TT) {
            const float* pn = preb + (size_t)(t + 1) * GATES;
            p_lo = pn[tid];
            p_hi = pn[256 + tid];
        }

        const ulonglong2* hu4 = (const ulonglong2*)hvec;
#pragma unroll
        for (int i = 0; i < 16; i++) {
            ull w0 = wsu[(2 * i) * 256 + tid];      // row tid, pair 32+2i
            ull w1 = wsu[(2 * i + 1) * 256 + tid];  // row tid, pair 33+2i
            // ha-side weights: regs for pairs 0..23, smem for pairs 24..31
            ull wa0, wa1;
            if (i < 12) {
                wa0 = ws_lo[2 * i];
                wa1 = ws_lo[2 * i + 1];
            } else {
                wa0 = wsu[(32 + 2 * (i - 12)) * 256 + tid];
                wa1 = wsu[(33 + 2 * (i - 12)) * 256 + tid];
            }
            ulonglong2 ha = hu4[i];                 // h pairs 2i, 2i+1 (16B bcast)
            ulonglong2 hb = hu4[16 + i];            // h pairs 32+2i, 33+2i
            ffma2(ar0, wr[2 * i],      ha.x);
            ffma2(ar1, wr[32 + 2 * i], hb.x);
            ffma2(as0, wa0,            ha.x);
            ffma2(as1, w0,             hb.x);
            ffma2(ar0, wr[2 * i + 1],  ha.y);
            ffma2(ar1, wr[33 + 2 * i], hb.y);
            ffma2(as0, wa1,            ha.y);
            ffma2(as1, w1,             hb.y);
        }

        float r0l, r0h, r1l, r1h, s0l, s0h, s1l, s1h;
        unpack2(ar0, r0l, r0h);
        unpack2(ar1, r1l, r1h);
        unpack2(as0, s0l, s0h);
        unpack2(as1, s1l, s1h);
        float acc_r = p_hi + ((r0l + r0h) + (r1l + r1h));
        float acc_s = p_lo + ((s0l + s0h) + (s1l + s1h));

        gbuf[tid]       = acc_s;
        gbuf[256 + tid] = acc_r;
        __syncthreads();

        if (tid < HID) {
            float gi = gbuf[tid];
            float gf = gbuf[128 + tid];
            float gg = gbuf[256 + tid];
            float go = gbuf[384 + tid];
            float iv = fast_sigmoid(gi);
            float fv = fast_sigmoid(gf);
            float gv = fast_tanh(gg);
            float ov = fast_sigmoid(go);
            c = fmaf(fv, c, iv * gv);
            float h = ov * fast_tanh(c);
            hvec[tid] = h;
            hsb[(size_t)t * HID + tid] = h;
        }
        __syncthreads();
    }
}

// ---------------------------------------------------------------------------
// Attention pooling (unchanged, verified)
// ---------------------------------------------------------------------------
__global__ void __launch_bounds__(128) attn_kernel(
    const float* __restrict__ hs,
    const float* __restrict__ w_attn,
    const float* __restrict__ b_attn,
    float* __restrict__ ctx)
{
    __shared__ float wv[HID];
    __shared__ float lg[TT];
    __shared__ float red[4];

    const int b = blockIdx.x;
    const int tid = threadIdx.x;

    wv[tid] = w_attn[tid];
    __syncthreads();

    const float* hb = hs + (size_t)b * TT * HID;
    const float battn = __ldg(&b_attn[0]);

    for (int t = tid; t < TT; t += 128) {
        const float4* row = (const float4*)(hb + (size_t)t * HID);
        const float4* wr4 = (const float4*)wv;
        float s = 0.f;
#pragma unroll
        for (int k = 0; k < HID / 4; k++) {
            float4 v = row[k];
            float4 w = wr4[k];
            s = fmaf(v.x, w.x, s);
            s = fmaf(v.y, w.y, s);
            s = fmaf(v.z, w.z, s);
            s = fmaf(v.w, w.w, s);
        }
        lg[t] = s + battn;
    }
    __syncthreads();

    float m = -1e30f;
    for (int t = tid; t < TT; t += 128) m = fmaxf(m, lg[t]);
#pragma unroll
    for (int o = 16; o > 0; o >>= 1) m = fmaxf(m, __shfl_xor_sync(0xffffffffu, m, o));
    if ((tid & 31) == 0) red[tid >> 5] = m;
    __syncthreads();
    m = fmaxf(fmaxf(red[0], red[1]), fmaxf(red[2], red[3]));
    __syncthreads();

    float z = 0.f;
    for (int t = tid; t < TT; t += 128) {
        float e = __expf(lg[t] - m);
        lg[t] = e;
        z += e;
    }
#pragma unroll
    for (int o = 16; o > 0; o >>= 1) z += __shfl_xor_sync(0xffffffffu, z, o);
    __syncthreads();
    if ((tid & 31) == 0) red[tid >> 5] = z;
    __syncthreads();
    z = red[0] + red[1] + red[2] + red[3];
    const float inv = 1.f / z;

    float acc = 0.f;
    for (int t = 0; t < TT; t++)
        acc = fmaf(lg[t], hb[(size_t)t * HID + tid], acc);
    ctx[(size_t)b * HID + tid] = acc * inv;
}

// ---------------------------------------------------------------------------
// MLP head (unchanged, verified)
// ---------------------------------------------------------------------------
__global__ void __launch_bounds__(128) mlp_kernel(
    const float* __restrict__ ctx,
    const float* __restrict__ w1, const float* __restrict__ b1,
    const float* __restrict__ w2, const float* __restrict__ b2,
    float* __restrict__ out)
{
    __shared__ float cs[HID];
    __shared__ float h1[64];

    const int b = blockIdx.x;
    const int tid = threadIdx.x;

    cs[tid] = ctx[(size_t)b * HID + tid];
    __syncthreads();

    if (tid < 64) {
        const float* wr = w1 + (size_t)tid * HID;
        float s = __ldg(&b1[tid]);
#pragma unroll 8
        for (int k = 0; k < HID; k++) s = fmaf(wr[k], cs[k], s);
        h1[tid] = fmaxf(s, 0.f);
    }
    __syncthreads();

    if (tid < FOUT) {
        const float* wr = w2 + (size_t)tid * 64;
        float s = __ldg(&b2[tid]);
#pragma unroll 8
        for (int k = 0; k < 64; k++) s = fmaf(wr[k], h1[k], s);
        out[(size_t)b * FOUT + tid] = s;
    }
}

// ---------------------------------------------------------------------------
// kernel_launch — wiring identical to R5-R13 (verified passing).
// ---------------------------------------------------------------------------
extern "C" void kernel_launch(void* const* d_in, const int* in_sizes, int n_in,
                              void* d_out, int out_size)
{
    const float *x = 0, *w_ih0 = 0, *w_ihr = 0, *w_hh = 0;
    const float *b_ih = 0, *b_hh = 0, *w_attn = 0, *b_attn = 0;
    const float *w1 = 0, *b1 = 0, *w2 = 0, *b2 = 0;

    int unit_bytes = 0, unit_elems = 0;
    for (int i = 0; i < n_in; i++) {
        if (in_sizes[i] == 8388608) unit_bytes = 1;
        if (in_sizes[i] == 2097152) unit_elems = 1;
    }

    if (unit_bytes || unit_elems) {
        const int div = unit_bytes ? 4 : 1;
        for (int i = 0; i < n_in; i++) {
            const float* p = (const float*)d_in[i];
            long long e = (long long)in_sizes[i] / div;
            switch (e) {
                case 2097152: x      = p; break;
                case 196608:  w_hh   = p; break;
                case 131072:  w_ihr  = p; break;
                case 16384:   w_ih0  = p; break;
                case 8192:    w1     = p; break;
                case 1536:    if (!b_ih) b_ih = p; else b_hh = p; break;
                case 256:     w2     = p; break;
                case 128:     w_attn = p; break;
                case 64:      b1     = p; break;
                case 4:       b2     = p; break;
                case 1:       b_attn = p; break;
                default: break;
            }
        }
    }

    if (n_in >= 12) {
        if (!x)      x      = (const float*)d_in[0];
        if (!w_ih0)  w_ih0  = (const float*)d_in[1];
        if (!w_ihr)  w_ihr  = (const float*)d_in[2];
        if (!w_hh)   w_hh   = (const float*)d_in[3];
        if (!b_ih)   b_ih   = (const float*)d_in[4];
        if (!b_hh)   b_hh   = (const float*)d_in[5];
        if (!w_attn) w_attn = (const float*)d_in[6];
        if (!b_attn) b_attn = (const float*)d_in[7];
        if (!w1)     w1     = (const float*)d_in[8];
        if (!b1)     b1     = (const float*)d_in[9];
        if (!w2)     w2     = (const float*)d_in[10];
        if (!b2)     b2     = (const float*)d_in[11];
    }

    float* out = (float*)d_out;

    float *pre = nullptr, *hs0 = nullptr, *hs1 = nullptr, *ctx = nullptr;
    cudaGetSymbolAddress((void**)&pre, g_pre);
    cudaGetSymbolAddress((void**)&hs0, g_hs0);
    cudaGetSymbolAddress((void**)&hs1, g_hs1);
    cudaGetSymbolAddress((void**)&ctx, g_ctx);

    const size_t lstm_smem = LSTM_SMEM_FLOATS * sizeof(float);  // ~84.5 KB
    cudaFuncSetAttribute(lstm_kernel,
                         cudaFuncAttributeMaxDynamicSharedMemorySize,
                         (int)lstm_smem);

    dim3 ggrid(BATCH * TT / GBM, GATES / GBN);   // 512 x 4

    // Layer 0
    gemm_bias_kernel<<<ggrid, 256>>>(x, w_ih0, b_ih + 0 * GATES, b_hh + 0 * GATES, pre, DIN);
    lstm_kernel<<<BATCH, 256, lstm_smem>>>(pre, w_hh + (size_t)0 * GATES * HID, hs0);

    // Layer 1
    gemm_bias_kernel<<<ggrid, 256>>>(hs0, w_ihr + (size_t)0 * GATES * HID,
                                     b_ih + 1 * GATES, b_hh + 1 * GATES, pre, HID);
    lstm_kernel<<<BATCH, 256, lstm_smem>>>(pre, w_hh + (size_t)1 * GATES * HID, hs1);

    // Layer 2
    gemm_bias_kernel<<<ggrid, 256>>>(hs1, w_ihr + (size_t)1 * GATES * HID,
                                     b_ih + 2 * GATES, b_hh + 2 * GATES, pre, HID);
    lstm_kernel<<<BATCH, 256, lstm_smem>>>(pre, w_hh + (size_t)2 * GATES * HID, hs0);

    // Attention pooling + MLP head
    attn_kernel<<<BATCH, 128>>>(hs0, w_attn, b_attn, ctx);
    mlp_kernel<<<BATCH, 128>>>(ctx, w1, b1, w2, b2, out);
}

// round 15
// speedup vs baseline: 1.0813x; 1.0501x over previous
#include <cuda_runtime.h>
#include <cuda_bf16.h>
#include <cstdint>

// Problem constants  (B,T,D,H,L,F = 128,512,32,128,3,4)
#define BATCH 128
#define TT    512
#define DIN   32
#define HID   128
#define GATES 512   // 4*HID
#define FOUT  4

typedef unsigned long long ull;

// ---------------------------------------------------------------------------
// Device scratch
// ---------------------------------------------------------------------------
__device__ float g_pre[BATCH * TT * GATES];
__device__ float g_hs0[BATCH * TT * HID];
__device__ float g_hs1[BATCH * TT * HID];
__device__ float g_ctx[BATCH * HID];

// ---------------------------------------------------------------------------
// Packed f32x2 helpers (sm_100+)
// ---------------------------------------------------------------------------
__device__ __forceinline__ ull pack2(float lo, float hi) {
    ull r;
    asm("mov.b64 %0, {%1, %2};" : "=l"(r) : "f"(lo), "f"(hi));
    return r;
}
__device__ __forceinline__ void unpack2(ull v, float& lo, float& hi) {
    asm("mov.b64 {%0, %1}, %2;" : "=f"(lo), "=f"(hi) : "l"(v));
}
__device__ __forceinline__ void ffma2(ull& d, ull a, ull b) {
    asm("fma.rn.f32x2 %0, %1, %2, %0;" : "+l"(d) : "l"(a), "l"(b));
}

// fast activations (MUFU-based) — verified (rel 2.5e-4)
__device__ __forceinline__ float fast_sigmoid(float x) {
    return __fdividef(1.f, 1.f + __expf(-x));
}
__device__ __forceinline__ float fast_tanh(float x) {
    float e = __expf(2.f * x);            // inf-safe
    return 1.f - __fdividef(2.f, e + 1.f);
}

// ---------------------------------------------------------------------------
// GEMM (FFMA2, double-buffered — measured best; ~85% of FFMA2 roofline)
// ---------------------------------------------------------------------------
#define GBM 128
#define GBN 128
#define GBK 16

__global__ void __launch_bounds__(256) gemm_bias_kernel(
    const float* __restrict__ A,
    const float* __restrict__ W,
    const float* __restrict__ bi,
    const float* __restrict__ bh,
    float* __restrict__ out,
    int K)
{
    __shared__ float As[2][GBK][GBM];
    __shared__ float Ws[2][GBK][GBN];

    const int bm = blockIdx.x;
    const int bn = blockIdx.y;
    const int tid = threadIdx.x;
    const int tx = tid & 15;
    const int ty = tid >> 4;

    const int lrow = tid >> 1;
    const int lq   = (tid & 1) * 2;

    const float* Ab = A + (size_t)(bm * GBM) * K;
    const float* Wb = W + (size_t)(bn * GBN) * K;

    ull acc[8][4];
    {
#pragma unroll
        for (int j = 0; j < 4; j++) {
            int n = bn * GBN + 2 * tx + 32 * j;
            ull bp = pack2(__ldg(&bi[n]) + __ldg(&bh[n]),
                           __ldg(&bi[n + 1]) + __ldg(&bh[n + 1]));
#pragma unroll
            for (int i = 0; i < 8; i++) acc[i][j] = bp;
        }
    }

    const int nb = K / GBK;

    float4 avr[2], wvr[2];
#pragma unroll
    for (int h = 0; h < 2; h++) {
        int kb = (lq + h) * 4;
        avr[h] = *(const float4*)(Ab + (size_t)lrow * K + kb);
        wvr[h] = *(const float4*)(Wb + (size_t)lrow * K + kb);
    }
#pragma unroll
    for (int h = 0; h < 2; h++) {
        int kb = (lq + h) * 4;
        As[0][kb + 0][lrow] = avr[h].x; As[0][kb + 1][lrow] = avr[h].y;
        As[0][kb + 2][lrow] = avr[h].z; As[0][kb + 3][lrow] = avr[h].w;
        Ws[0][kb + 0][lrow] = wvr[h].x; Ws[0][kb + 1][lrow] = wvr[h].y;
        Ws[0][kb + 2][lrow] = wvr[h].z; Ws[0][kb + 3][lrow] = wvr[h].w;
    }
    __syncthreads();

    for (int it = 0; it < nb; it++) {
        const int cur = it & 1;
        const bool has_next = (it + 1 < nb);

        if (has_next) {
            int k0 = (it + 1) * GBK;
#pragma unroll
            for (int h = 0; h < 2; h++) {
                int kb = (lq + h) * 4;
                avr[h] = *(const float4*)(Ab + (size_t)lrow * K + k0 + kb);
                wvr[h] = *(const float4*)(Wb + (size_t)lrow * K + k0 + kb);
            }
        }

#pragma unroll
        for (int k = 0; k < GBK; k++) {
            const ull* wrow = (const ull*)&Ws[cur][k][0];
            ull w0 = wrow[tx];
            ull w1 = wrow[tx + 16];
            ull w2 = wrow[tx + 32];
            ull w3 = wrow[tx + 48];
            float4 a0 = *(const float4*)&As[cur][k][ty * 8];
            float4 a1 = *(const float4*)&As[cur][k][ty * 8 + 4];
            ull ap[8];
            ap[0] = pack2(a0.x, a0.x); ap[1] = pack2(a0.y, a0.y);
            ap[2] = pack2(a0.z, a0.z); ap[3] = pack2(a0.w, a0.w);
            ap[4] = pack2(a1.x, a1.x); ap[5] = pack2(a1.y, a1.y);
            ap[6] = pack2(a1.z, a1.z); ap[7] = pack2(a1.w, a1.w);
#pragma unroll
            for (int i = 0; i < 8; i++) {
                ffma2(acc[i][0], ap[i], w0);
                ffma2(acc[i][1], ap[i], w1);
                ffma2(acc[i][2], ap[i], w2);
                ffma2(acc[i][3], ap[i], w3);
            }
        }

        if (has_next) {
            const int alt = cur ^ 1;
#pragma unroll
            for (int h = 0; h < 2; h++) {
                int kb = (lq + h) * 4;
                As[alt][kb + 0][lrow] = avr[h].x; As[alt][kb + 1][lrow] = avr[h].y;
                As[alt][kb + 2][lrow] = avr[h].z; As[alt][kb + 3][lrow] = avr[h].w;
                Ws[alt][kb + 0][lrow] = wvr[h].x; Ws[alt][kb + 1][lrow] = wvr[h].y;
                Ws[alt][kb + 2][lrow] = wvr[h].z; Ws[alt][kb + 3][lrow] = wvr[h].w;
            }
            __syncthreads();
        }
    }

    const int m0 = bm * GBM + ty * 8;
#pragma unroll
    for (int i = 0; i < 8; i++) {
#pragma unroll
        for (int j = 0; j < 4; j++) {
            float lo, hi;
            unpack2(acc[i][j], lo, hi);
            int n = bn * GBN + 2 * tx + 32 * j;
            *(float2*)&out[(size_t)(m0 + i) * GATES + n] = make_float2(lo, hi);
        }
    }
}

// ---------------------------------------------------------------------------
// LSTM v7: k-split across 512 threads (16 warps/SM) to hide latency.
// Thread idx = (half = idx>>8, tid = idx&255). Thread computes the HALF
// dot-product (k-pairs 32h..32h+31) of gate rows {tid, 256+tid}:
//   - acc_r row 256+tid: 32 pairs in regs (wr)
//   - acc_s row tid: 16 pairs in regs (ws_lo), 16 pairs in smem (wsu)
// Partials combined in the gbuf exchange (sbuf[2][512]); activation threads
// (idx<128) sum both halves. Weight smem bytes/step unchanged (64KB).
// Same math per pair -> same numerics class as R11/R12.
// ---------------------------------------------------------------------------
#define LTHREADS 512
#define LSTM_SMEM_BYTES (16 * 512 * 8 + 1024 * 4 + HID * 4)   // 64KB wsu + 4KB sbuf + hvec

__global__ void __launch_bounds__(LTHREADS, 1) lstm_kernel(
    const float* __restrict__ pre,   // [B][T][512]
    const float* __restrict__ whh,   // [512][128]
    float* __restrict__ hs)          // [B][T][128]
{
    extern __shared__ char smemraw[];
    ull*   wsu  = (ull*)smemraw;                       // [16][512]
    float* sbuf = (float*)(smemraw + 16 * 512 * 8);    // [2][512] partials
    float* hvec = sbuf + 1024;                         // [128], 16B aligned

    const int b = blockIdx.x;
    const int idx = threadIdx.x;
    const int half = idx >> 8;       // 0 or 1 (k-half)
    const int tid = idx & 255;       // gate row pair id

    // register weights (this thread's k-half only)
    ull wr[32];     // row 256+tid, k-pairs 32h .. 32h+31
    ull ws_lo[16];  // row tid,     k-pairs 32h .. 32h+15
    {
        const float4* r4 = (const float4*)(whh + (size_t)(256 + tid) * HID);
#pragma unroll
        for (int i = 0; i < 16; i++) {
            float4 v = r4[16 * half + i];
            wr[2 * i]     = pack2(v.x, v.y);
            wr[2 * i + 1] = pack2(v.z, v.w);
        }
        const float4* s4 = (const float4*)(whh + (size_t)tid * HID);
#pragma unroll
        for (int i = 0; i < 8; i++) {
            float4 v = s4[16 * half + i];
            ws_lo[2 * i]     = pack2(v.x, v.y);
            ws_lo[2 * i + 1] = pack2(v.z, v.w);
        }
        // smem: row tid, k-pairs 32h+16 .. 32h+31  -> wsu[j][idx], j=0..15
#pragma unroll
        for (int i = 0; i < 8; i++) {
            float4 v = s4[16 * half + 8 + i];
            wsu[(2 * i) * 512 + idx]     = pack2(v.x, v.y);
            wsu[(2 * i + 1) * 512 + idx] = pack2(v.z, v.w);
        }
    }
    if (idx < HID) hvec[idx] = 0.f;
    float c = 0.f;                  // live only for idx<128
    __syncthreads();

    const float* preb = pre + (size_t)b * TT * GATES;
    float* hsb = hs + (size_t)b * TT * HID;

    // pre-activation prefetch: half 0 only (half 1 contributes zero-init partials)
    float p_s = 0.f, p_r = 0.f;
    if (half == 0) { p_s = preb[tid]; p_r = preb[256 + tid]; }

#pragma unroll 1
    for (int t = 0; t < TT; t++) {
        ull ar0 = 0, ar1 = 0, as0 = 0, as1 = 0;

        const float c_s = p_s, c_r = p_r;
        if (half == 0 && t + 1 < TT) {
            const float* pn = preb + (size_t)(t + 1) * GATES;
            p_s = pn[tid];
            p_r = pn[256 + tid];
        }

        // h pairs for this half: ulonglong2 indices 16h .. 16h+15
        const ulonglong2* hu4 = (const ulonglong2*)hvec;
#pragma unroll
        for (int i = 0; i < 16; i++) {
            ulonglong2 ha = hu4[16 * half + i];       // pairs 32h+2i, 32h+2i+1
            ffma2(ar0, wr[2 * i],     ha.x);
            ffma2(ar1, wr[2 * i + 1], ha.y);
            if (i < 8) {
                ffma2(as0, ws_lo[2 * i],     ha.x);
                ffma2(as1, ws_lo[2 * i + 1], ha.y);
            } else {
                ull w0 = wsu[(2 * (i - 8)) * 512 + idx];
                ull w1 = wsu[(2 * (i - 8) + 1) * 512 + idx];
                ffma2(as0, w0, ha.x);
                ffma2(as1, w1, ha.y);
            }
        }

        float xl, xh, yl, yh;
        unpack2(ar0, xl, xh); unpack2(ar1, yl, yh);
        float part_r = c_r + ((xl + xh) + (yl + yh));
        unpack2(as0, xl, xh); unpack2(as1, yl, yh);
        float part_s = c_s + ((xl + xh) + (yl + yh));

        // partials: sbuf[half*512 + {tid | 256+tid}]
        sbuf[half * 512 + tid]       = part_s;
        sbuf[half * 512 + 256 + tid] = part_r;
        __syncthreads();

        if (idx < HID) {
            const int u = idx;
            float gi = sbuf[u]       + sbuf[512 + u];
            float gf = sbuf[128 + u] + sbuf[640 + u];
            float gg = sbuf[256 + u] + sbuf[768 + u];
            float go = sbuf[384 + u] + sbuf[896 + u];
            float iv = fast_sigmoid(gi);
            float fv = fast_sigmoid(gf);
            float gv = fast_tanh(gg);
            float ov = fast_sigmoid(go);
            c = fmaf(fv, c, iv * gv);
            float h = ov * fast_tanh(c);
            hvec[u] = h;
            hsb[(size_t)t * HID + u] = h;
        }
        __syncthreads();
    }
}

// ---------------------------------------------------------------------------
// Attention pooling (unchanged, verified)
// ---------------------------------------------------------------------------
__global__ void __launch_bounds__(128) attn_kernel(
    const float* __restrict__ hs,
    const float* __restrict__ w_attn,
    const float* __restrict__ b_attn,
    float* __restrict__ ctx)
{
    __shared__ float wv[HID];
    __shared__ float lg[TT];
    __shared__ float red[4];

    const int b = blockIdx.x;
    const int tid = threadIdx.x;

    wv[tid] = w_attn[tid];
    __syncthreads();

    const float* hb = hs + (size_t)b * TT * HID;
    const float battn = __ldg(&b_attn[0]);

    for (int t = tid; t < TT; t += 128) {
        const float4* row = (const float4*)(hb + (size_t)t * HID);
        const float4* wr4 = (const float4*)wv;
        float s = 0.f;
#pragma unroll
        for (int k = 0; k < HID / 4; k++) {
            float4 v = row[k];
            float4 w = wr4[k];
            s = fmaf(v.x, w.x, s);
            s = fmaf(v.y, w.y, s);
            s = fmaf(v.z, w.z, s);
            s = fmaf(v.w, w.w, s);
        }
        lg[t] = s + battn;
    }
    __syncthreads();

    float m = -1e30f;
    for (int t = tid; t < TT; t += 128) m = fmaxf(m, lg[t]);
#pragma unroll
    for (int o = 16; o > 0; o >>= 1) m = fmaxf(m, __shfl_xor_sync(0xffffffffu, m, o));
    if ((tid & 31) == 0) red[tid >> 5] = m;
    __syncthreads();
    m = fmaxf(fmaxf(red[0], red[1]), fmaxf(red[2], red[3]));
    __syncthreads();

    float z = 0.f;
    for (int t = tid; t < TT; t += 128) {
        float e = __expf(lg[t] - m);
        lg[t] = e;
        z += e;
    }
#pragma unroll
    for (int o = 16; o > 0; o >>= 1) z += __shfl_xor_sync(0xffffffffu, z, o);
    __syncthreads();
    if ((tid & 31) == 0) red[tid >> 5] = z;
    __syncthreads();
    z = red[0] + red[1] + red[2] + red[3];
    const float inv = 1.f / z;

    float acc = 0.f;
    for (int t = 0; t < TT; t++)
        acc = fmaf(lg[t], hb[(size_t)t * HID + tid], acc);
    ctx[(size_t)b * HID + tid] = acc * inv;
}

// ---------------------------------------------------------------------------
// MLP head (unchanged, verified)
// ---------------------------------------------------------------------------
__global__ void __launch_bounds__(128) mlp_kernel(
    const float* __restrict__ ctx,
    const float* __restrict__ w1, const float* __restrict__ b1,
    const float* __restrict__ w2, const float* __restrict__ b2,
    float* __restrict__ out)
{
    __shared__ float cs[HID];
    __shared__ float h1[64];

    const int b = blockIdx.x;
    const int tid = threadIdx.x;

    cs[tid] = ctx[(size_t)b * HID + tid];
    __syncthreads();

    if (tid < 64) {
        const float* wr = w1 + (size_t)tid * HID;
        float s = __ldg(&b1[tid]);
#pragma unroll 8
        for (int k = 0; k < HID; k++) s = fmaf(wr[k], cs[k], s);
        h1[tid] = fmaxf(s, 0.f);
    }
    __syncthreads();

    if (tid < FOUT) {
        const float* wr = w2 + (size_t)tid * 64;
        float s = __ldg(&b2[tid]);
#pragma unroll 8
        for (int k = 0; k < 64; k++) s = fmaf(wr[k], h1[k], s);
        out[(size_t)b * FOUT + tid] = s;
    }
}

// ---------------------------------------------------------------------------
// kernel_launch — wiring identical to R5-R14 (verified passing).
// ---------------------------------------------------------------------------
extern "C" void kernel_launch(void* const* d_in, const int* in_sizes, int n_in,
                              void* d_out, int out_size)
{
    const float *x = 0, *w_ih0 = 0, *w_ihr = 0, *w_hh = 0;
    const float *b_ih = 0, *b_hh = 0, *w_attn = 0, *b_attn = 0;
    const float *w1 = 0, *b1 = 0, *w2 = 0, *b2 = 0;

    int unit_bytes = 0, unit_elems = 0;
    for (int i = 0; i < n_in; i++) {
        if (in_sizes[i] == 8388608) unit_bytes = 1;
        if (in_sizes[i] == 2097152) unit_elems = 1;
    }

    if (unit_bytes || unit_elems) {
        const int div = unit_bytes ? 4 : 1;
        for (int i = 0; i < n_in; i++) {
            const float* p = (const float*)d_in[i];
            long long e = (long long)in_sizes[i] / div;
            switch (e) {
                case 2097152: x      = p; break;
                case 196608:  w_hh   = p; break;
                case 131072:  w_ihr  = p; break;
                case 16384:   w_ih0  = p; break;
                case 8192:    w1     = p; break;
                case 1536:    if (!b_ih) b_ih = p; else b_hh = p; break;
                case 256:     w2     = p; break;
                case 128:     w_attn = p; break;
                case 64:      b1     = p; break;
                case 4:       b2     = p; break;
                case 1:       b_attn = p; break;
                default: break;
            }
        }
    }

    if (n_in >= 12) {
        if (!x)      x      = (const float*)d_in[0];
        if (!w_ih0)  w_ih0  = (const float*)d_in[1];
        if (!w_ihr)  w_ihr  = (const float*)d_in[2];
        if (!w_hh)   w_hh   = (const float*)d_in[3];
        if (!b_ih)   b_ih   = (const float*)d_in[4];
        if (!b_hh)   b_hh   = (const float*)d_in[5];
        if (!w_attn) w_attn = (const float*)d_in[6];
        if (!b_attn) b_attn = (const float*)d_in[7];
        if (!w1)     w1     = (const float*)d_in[8];
        if (!b1)     b1     = (const float*)d_in[9];
        if (!w2)     w2     = (const float*)d_in[10];
        if (!b2)     b2     = (const float*)d_in[11];
    }

    float* out = (float*)d_out;

    float *pre = nullptr, *hs0 = nullptr, *hs1 = nullptr, *ctx = nullptr;
    cudaGetSymbolAddress((void**)&pre, g_pre);
    cudaGetSymbolAddress((void**)&hs0, g_hs0);
    cudaGetSymbolAddress((void**)&hs1, g_hs1);
    cudaGetSymbolAddress((void**)&ctx, g_ctx);

    cudaFuncSetAttribute(lstm_kernel,
                         cudaFuncAttributeMaxDynamicSharedMemorySize,
                         LSTM_SMEM_BYTES);

    dim3 ggrid(BATCH * TT / GBM, GATES / GBN);   // 512 x 4

    // Layer 0
    gemm_bias_kernel<<<ggrid, 256>>>(x, w_ih0, b_ih + 0 * GATES, b_hh + 0 * GATES, pre, DIN);
    lstm_kernel<<<BATCH, LTHREADS, LSTM_SMEM_BYTES>>>(pre, w_hh + (size_t)0 * GATES * HID, hs0);

    // Layer 1
    gemm_bias_kernel<<<ggrid, 256>>>(hs0, w_ihr + (size_t)0 * GATES * HID,
                                     b_ih + 1 * GATES, b_hh + 1 * GATES, pre, HID);
    lstm_kernel<<<BATCH, LTHREADS, LSTM_SMEM_BYTES>>>(pre, w_hh + (size_t)1 * GATES * HID, hs1);

    // Layer 2
    gemm_bias_kernel<<<ggrid, 256>>>(hs1, w_ihr + (size_t)1 * GATES * HID,
                                     b_ih + 2 * GATES, b_hh + 2 * GATES, pre, HID);
    lstm_kernel<<<BATCH, LTHREADS, LSTM_SMEM_BYTES>>>(pre, w_hh + (size_t)2 * GATES * HID, hs0);

    // Attention pooling + MLP head
    attn_kernel<<<BATCH, 128>>>(hs0, w_attn, b_attn, ctx);
    mlp_kernel<<<BATCH, 128>>>(ctx, w1, b1, w2, b2, out);
}

// round 16
// speedup vs baseline: 1.1395x; 1.0538x over previous
#include <cuda_runtime.h>
#include <cuda_bf16.h>
#include <cstdint>

// Problem constants  (B,T,D,H,L,F = 128,512,32,128,3,4)
#define BATCH 128
#define TT    512
#define DIN   32
#define HID   128
#define GATES 512   // 4*HID
#define FOUT  4

typedef unsigned long long ull;

// ---------------------------------------------------------------------------
// Device scratch
// ---------------------------------------------------------------------------
__device__ float g_pre[BATCH * TT * GATES];
__device__ float g_hs0[BATCH * TT * HID];
__device__ float g_hs1[BATCH * TT * HID];

// ---------------------------------------------------------------------------
// Packed f32x2 helpers (sm_100+)
// ---------------------------------------------------------------------------
__device__ __forceinline__ ull pack2(float lo, float hi) {
    ull r;
    asm("mov.b64 %0, {%1, %2};" : "=l"(r) : "f"(lo), "f"(hi));
    return r;
}
__device__ __forceinline__ void unpack2(ull v, float& lo, float& hi) {
    asm("mov.b64 {%0, %1}, %2;" : "=f"(lo), "=f"(hi) : "l"(v));
}
__device__ __forceinline__ void ffma2(ull& d, ull a, ull b) {
    asm("fma.rn.f32x2 %0, %1, %2, %0;" : "+l"(d) : "l"(a), "l"(b));
}

// MUFU.TANH-based activations (single-MUFU tanh, sm_75+)
__device__ __forceinline__ float mufu_tanh(float x) {
    float y;
    asm("tanh.approx.f32 %0, %1;" : "=f"(y) : "f"(x));
    return y;
}
__device__ __forceinline__ float mufu_sigmoid(float x) {
    return fmaf(0.5f, mufu_tanh(0.5f * x), 0.5f);
}

// ---------------------------------------------------------------------------
// GEMM (FFMA2, double-buffered — measured best; ~85% of FFMA2 roofline)
// ---------------------------------------------------------------------------
#define GBM 128
#define GBN 128
#define GBK 16

__global__ void __launch_bounds__(256) gemm_bias_kernel(
    const float* __restrict__ A,
    const float* __restrict__ W,
    const float* __restrict__ bi,
    const float* __restrict__ bh,
    float* __restrict__ out,
    int K)
{
    __shared__ float As[2][GBK][GBM];
    __shared__ float Ws[2][GBK][GBN];

    const int bm = blockIdx.x;
    const int bn = blockIdx.y;
    const int tid = threadIdx.x;
    const int tx = tid & 15;
    const int ty = tid >> 4;

    const int lrow = tid >> 1;
    const int lq   = (tid & 1) * 2;

    const float* Ab = A + (size_t)(bm * GBM) * K;
    const float* Wb = W + (size_t)(bn * GBN) * K;

    ull acc[8][4];
    {
#pragma unroll
        for (int j = 0; j < 4; j++) {
            int n = bn * GBN + 2 * tx + 32 * j;
            ull bp = pack2(__ldg(&bi[n]) + __ldg(&bh[n]),
                           __ldg(&bi[n + 1]) + __ldg(&bh[n + 1]));
#pragma unroll
            for (int i = 0; i < 8; i++) acc[i][j] = bp;
        }
    }

    const int nb = K / GBK;

    float4 avr[2], wvr[2];
#pragma unroll
    for (int h = 0; h < 2; h++) {
        int kb = (lq + h) * 4;
        avr[h] = *(const float4*)(Ab + (size_t)lrow * K + kb);
        wvr[h] = *(const float4*)(Wb + (size_t)lrow * K + kb);
    }
#pragma unroll
    for (int h = 0; h < 2; h++) {
        int kb = (lq + h) * 4;
        As[0][kb + 0][lrow] = avr[h].x; As[0][kb + 1][lrow] = avr[h].y;
        As[0][kb + 2][lrow] = avr[h].z; As[0][kb + 3][lrow] = avr[h].w;
        Ws[0][kb + 0][lrow] = wvr[h].x; Ws[0][kb + 1][lrow] = wvr[h].y;
        Ws[0][kb + 2][lrow] = wvr[h].z; Ws[0][kb + 3][lrow] = wvr[h].w;
    }
    __syncthreads();

    for (int it = 0; it < nb; it++) {
        const int cur = it & 1;
        const bool has_next = (it + 1 < nb);

        if (has_next) {
            int k0 = (it + 1) * GBK;
#pragma unroll
            for (int h = 0; h < 2; h++) {
                int kb = (lq + h) * 4;
                avr[h] = *(const float4*)(Ab + (size_t)lrow * K + k0 + kb);
                wvr[h] = *(const float4*)(Wb + (size_t)lrow * K + k0 + kb);
            }
        }

#pragma unroll
        for (int k = 0; k < GBK; k++) {
            const ull* wrow = (const ull*)&Ws[cur][k][0];
            ull w0 = wrow[tx];
            ull w1 = wrow[tx + 16];
            ull w2 = wrow[tx + 32];
            ull w3 = wrow[tx + 48];
            float4 a0 = *(const float4*)&As[cur][k][ty * 8];
            float4 a1 = *(const float4*)&As[cur][k][ty * 8 + 4];
            ull ap[8];
            ap[0] = pack2(a0.x, a0.x); ap[1] = pack2(a0.y, a0.y);
            ap[2] = pack2(a0.z, a0.z); ap[3] = pack2(a0.w, a0.w);
            ap[4] = pack2(a1.x, a1.x); ap[5] = pack2(a1.y, a1.y);
            ap[6] = pack2(a1.z, a1.z); ap[7] = pack2(a1.w, a1.w);
#pragma unroll
            for (int i = 0; i < 8; i++) {
                ffma2(acc[i][0], ap[i], w0);
                ffma2(acc[i][1], ap[i], w1);
                ffma2(acc[i][2], ap[i], w2);
                ffma2(acc[i][3], ap[i], w3);
            }
        }

        if (has_next) {
            const int alt = cur ^ 1;
#pragma unroll
            for (int h = 0; h < 2; h++) {
                int kb = (lq + h) * 4;
                As[alt][kb + 0][lrow] = avr[h].x; As[alt][kb + 1][lrow] = avr[h].y;
                As[alt][kb + 2][lrow] = avr[h].z; As[alt][kb + 3][lrow] = avr[h].w;
                Ws[alt][kb + 0][lrow] = wvr[h].x; Ws[alt][kb + 1][lrow] = wvr[h].y;
                Ws[alt][kb + 2][lrow] = wvr[h].z; Ws[alt][kb + 3][lrow] = wvr[h].w;
            }
            __syncthreads();
        }
    }

    const int m0 = bm * GBM + ty * 8;
#pragma unroll
    for (int i = 0; i < 8; i++) {
#pragma unroll
        for (int j = 0; j < 4; j++) {
            float lo, hi;
            unpack2(acc[i][j], lo, hi);
            int n = bn * GBN + 2 * tx + 32 * j;
            *(float2*)&out[(size_t)(m0 + i) * GATES + n] = make_float2(lo, hi);
        }
    }
}

// ---------------------------------------------------------------------------
// LSTM v7 (R15 structure, measured best/tied) with MUFU.TANH activations.
// k-split across 512 threads; thread idx = (half = idx>>8, tid = idx&255).
// ---------------------------------------------------------------------------
#define LTHREADS 512
#define LSTM_SMEM_BYTES (16 * 512 * 8 + 1024 * 4 + HID * 4)

__global__ void __launch_bounds__(LTHREADS, 1) lstm_kernel(
    const float* __restrict__ pre,   // [B][T][512]
    const float* __restrict__ whh,   // [512][128]
    float* __restrict__ hs)          // [B][T][128]
{
    extern __shared__ char smemraw[];
    ull*   wsu  = (ull*)smemraw;                       // [16][512]
    float* sbuf = (float*)(smemraw + 16 * 512 * 8);    // [2][512] partials
    float* hvec = sbuf + 1024;                         // [128], 16B aligned

    const int b = blockIdx.x;
    const int idx = threadIdx.x;
    const int half = idx >> 8;       // 0 or 1 (k-half)
    const int tid = idx & 255;       // gate row pair id

    // register weights (this thread's k-half only)
    ull wr[32];     // row 256+tid, k-pairs 32h .. 32h+31
    ull ws_lo[16];  // row tid,     k-pairs 32h .. 32h+15
    {
        const float4* r4 = (const float4*)(whh + (size_t)(256 + tid) * HID);
#pragma unroll
        for (int i = 0; i < 16; i++) {
            float4 v = r4[16 * half + i];
            wr[2 * i]     = pack2(v.x, v.y);
            wr[2 * i + 1] = pack2(v.z, v.w);
        }
        const float4* s4 = (const float4*)(whh + (size_t)tid * HID);
#pragma unroll
        for (int i = 0; i < 8; i++) {
            float4 v = s4[16 * half + i];
            ws_lo[2 * i]     = pack2(v.x, v.y);
            ws_lo[2 * i + 1] = pack2(v.z, v.w);
        }
        // smem: row tid, k-pairs 32h+16 .. 32h+31  -> wsu[j][idx], j=0..15
#pragma unroll
        for (int i = 0; i < 8; i++) {
            float4 v = s4[16 * half + 8 + i];
            wsu[(2 * i) * 512 + idx]     = pack2(v.x, v.y);
            wsu[(2 * i + 1) * 512 + idx] = pack2(v.z, v.w);
        }
    }
    if (idx < HID) hvec[idx] = 0.f;
    float c = 0.f;                  // live only for idx<128
    __syncthreads();

    const float* preb = pre + (size_t)b * TT * GATES;
    float* hsb = hs + (size_t)b * TT * HID;

    // pre-activation prefetch: half 0 only
    float p_s = 0.f, p_r = 0.f;
    if (half == 0) { p_s = preb[tid]; p_r = preb[256 + tid]; }

#pragma unroll 1
    for (int t = 0; t < TT; t++) {
        ull ar0 = 0, ar1 = 0, as0 = 0, as1 = 0;

        const float c_s = p_s, c_r = p_r;
        if (half == 0 && t + 1 < TT) {
            const float* pn = preb + (size_t)(t + 1) * GATES;
            p_s = pn[tid];
            p_r = pn[256 + tid];
        }

        const ulonglong2* hu4 = (const ulonglong2*)hvec;
#pragma unroll
        for (int i = 0; i < 16; i++) {
            ulonglong2 ha = hu4[16 * half + i];       // pairs 32h+2i, 32h+2i+1
            ffma2(ar0, wr[2 * i],     ha.x);
            ffma2(ar1, wr[2 * i + 1], ha.y);
            if (i < 8) {
                ffma2(as0, ws_lo[2 * i],     ha.x);
                ffma2(as1, ws_lo[2 * i + 1], ha.y);
            } else {
                ull w0 = wsu[(2 * (i - 8)) * 512 + idx];
                ull w1 = wsu[(2 * (i - 8) + 1) * 512 + idx];
                ffma2(as0, w0, ha.x);
                ffma2(as1, w1, ha.y);
            }
        }

        float xl, xh, yl, yh;
        unpack2(ar0, xl, xh); unpack2(ar1, yl, yh);
        float part_r = c_r + ((xl + xh) + (yl + yh));
        unpack2(as0, xl, xh); unpack2(as1, yl, yh);
        float part_s = c_s + ((xl + xh) + (yl + yh));

        sbuf[half * 512 + tid]       = part_s;
        sbuf[half * 512 + 256 + tid] = part_r;
        __syncthreads();

        if (idx < HID) {
            const int u = idx;
            float gi = sbuf[u]       + sbuf[512 + u];
            float gf = sbuf[128 + u] + sbuf[640 + u];
            float gg = sbuf[256 + u] + sbuf[768 + u];
            float go = sbuf[384 + u] + sbuf[896 + u];
            float iv = mufu_sigmoid(gi);
            float fv = mufu_sigmoid(gf);
            float gv = mufu_tanh(gg);
            float ov = mufu_sigmoid(go);
            c = fmaf(fv, c, iv * gv);
            float h = ov * mufu_tanh(c);
            hvec[u] = h;
            hsb[(size_t)t * HID + u] = h;
        }
        __syncthreads();
    }
}

// ---------------------------------------------------------------------------
// Fused attention pooling + MLP head: one block per batch, 128 threads.
// ctx never leaves smem.
// ---------------------------------------------------------------------------
__global__ void __launch_bounds__(128) attn_mlp_kernel(
    const float* __restrict__ hs,
    const float* __restrict__ w_attn,
    const float* __restrict__ b_attn,
    const float* __restrict__ w1, const float* __restrict__ b1,
    const float* __restrict__ w2, const float* __restrict__ b2,
    float* __restrict__ out)
{
    __shared__ float wv[HID];
    __shared__ float lg[TT];
    __shared__ float red[4];
    __shared__ float cs[HID];
    __shared__ float h1[64];

    const int b = blockIdx.x;
    const int tid = threadIdx.x;

    wv[tid] = w_attn[tid];
    __syncthreads();

    const float* hb = hs + (size_t)b * TT * HID;
    const float battn = __ldg(&b_attn[0]);

    for (int t = tid; t < TT; t += 128) {
        const float4* row = (const float4*)(hb + (size_t)t * HID);
        const float4* wr4 = (const float4*)wv;
        float s = 0.f;
#pragma unroll
        for (int k = 0; k < HID / 4; k++) {
            float4 v = row[k];
            float4 w = wr4[k];
            s = fmaf(v.x, w.x, s);
            s = fmaf(v.y, w.y, s);
            s = fmaf(v.z, w.z, s);
            s = fmaf(v.w, w.w, s);
        }
        lg[t] = s + battn;
    }
    __syncthreads();

    float m = -1e30f;
    for (int t = tid; t < TT; t += 128) m = fmaxf(m, lg[t]);
#pragma unroll
    for (int o = 16; o > 0; o >>= 1) m = fmaxf(m, __shfl_xor_sync(0xffffffffu, m, o));
    if ((tid & 31) == 0) red[tid >> 5] = m;
    __syncthreads();
    m = fmaxf(fmaxf(red[0], red[1]), fmaxf(red[2], red[3]));
    __syncthreads();

    float z = 0.f;
    for (int t = tid; t < TT; t += 128) {
        float e = __expf(lg[t] - m);
        lg[t] = e;
        z += e;
    }
#pragma unroll
    for (int o = 16; o > 0; o >>= 1) z += __shfl_xor_sync(0xffffffffu, z, o);
    __syncthreads();
    if ((tid & 31) == 0) red[tid >> 5] = z;
    __syncthreads();
    z = red[0] + red[1] + red[2] + red[3];
    const float inv = 1.f / z;

    float acc = 0.f;
    for (int t = 0; t < TT; t++)
        acc = fmaf(lg[t], hb[(size_t)t * HID + tid], acc);
    cs[tid] = acc * inv;
    __syncthreads();

    if (tid < 64) {
        const float* wr = w1 + (size_t)tid * HID;
        float s = __ldg(&b1[tid]);
#pragma unroll 8
        for (int k = 0; k < HID; k++) s = fmaf(wr[k], cs[k], s);
        h1[tid] = fmaxf(s, 0.f);
    }
    __syncthreads();

    if (tid < FOUT) {
        const float* wr = w2 + (size_t)tid * 64;
        float s = __ldg(&b2[tid]);
#pragma unroll 8
        for (int k = 0; k < 64; k++) s = fmaf(wr[k], h1[k], s);
        out[(size_t)b * FOUT + tid] = s;
    }
}

// ---------------------------------------------------------------------------
// kernel_launch — wiring identical to R5-R15 (verified passing).
// ---------------------------------------------------------------------------
extern "C" void kernel_launch(void* const* d_in, const int* in_sizes, int n_in,
                              void* d_out, int out_size)
{
    const float *x = 0, *w_ih0 = 0, *w_ihr = 0, *w_hh = 0;
    const float *b_ih = 0, *b_hh = 0, *w_attn = 0, *b_attn = 0;
    const float *w1 = 0, *b1 = 0, *w2 = 0, *b2 = 0;

    int unit_bytes = 0, unit_elems = 0;
    for (int i = 0; i < n_in; i++) {
        if (in_sizes[i] == 8388608) unit_bytes = 1;
        if (in_sizes[i] == 2097152) unit_elems = 1;
    }

    if (unit_bytes || unit_elems) {
        const int div = unit_bytes ? 4 : 1;
        for (int i = 0; i < n_in; i++) {
            const float* p = (const float*)d_in[i];
            long long e = (long long)in_sizes[i] / div;
            switch (e) {
                case 2097152: x      = p; break;
                case 196608:  w_hh   = p; break;
                case 131072:  w_ihr  = p; break;
                case 16384:   w_ih0  = p; break;
                case 8192:    w1     = p; break;
                case 1536:    if (!b_ih) b_ih = p; else b_hh = p; break;
                case 256:     w2     = p; break;
                case 128:     w_attn = p; break;
                case 64:      b1     = p; break;
                case 4:       b2     = p; break;
                case 1:       b_attn = p; break;
                default: break;
            }
        }
    }

    if (n_in >= 12) {
        if (!x)      x      = (const float*)d_in[0];
        if (!w_ih0)  w_ih0  = (const float*)d_in[1];
        if (!w_ihr)  w_ihr  = (const float*)d_in[2];
        if (!w_hh)   w_hh   = (const float*)d_in[3];
        if (!b_ih)   b_ih   = (const float*)d_in[4];
        if (!b_hh)   b_hh   = (const float*)d_in[5];
        if (!w_attn) w_attn = (const float*)d_in[6];
        if (!b_attn) b_attn = (const float*)d_in[7];
        if (!w1)     w1     = (const float*)d_in[8];
        if (!b1)     b1     = (const float*)d_in[9];
        if (!w2)     w2     = (const float*)d_in[10];
        if (!b2)     b2     = (const float*)d_in[11];
    }

    float* out = (float*)d_out;

    float *pre = nullptr, *hs0 = nullptr, *hs1 = nullptr;
    cudaGetSymbolAddress((void**)&pre, g_pre);
    cudaGetSymbolAddress((void**)&hs0, g_hs0);
    cudaGetSymbolAddress((void**)&hs1, g_hs1);

    cudaFuncSetAttribute(lstm_kernel,
                         cudaFuncAttributeMaxDynamicSharedMemorySize,
                         LSTM_SMEM_BYTES);

    dim3 ggrid(BATCH * TT / GBM, GATES / GBN);   // 512 x 4

    // Layer 0
    gemm_bias_kernel<<<ggrid, 256>>>(x, w_ih0, b_ih + 0 * GATES, b_hh + 0 * GATES, pre, DIN);
    lstm_kernel<<<BATCH, LTHREADS, LSTM_SMEM_BYTES>>>(pre, w_hh + (size_t)0 * GATES * HID, hs0);

    // Layer 1
    gemm_bias_kernel<<<ggrid, 256>>>(hs0, w_ihr + (size_t)0 * GATES * HID,
                                     b_ih + 1 * GATES, b_hh + 1 * GATES, pre, HID);
    lstm_kernel<<<BATCH, LTHREADS, LSTM_SMEM_BYTES>>>(pre, w_hh + (size_t)1 * GATES * HID, hs1);

    // Layer 2
    gemm_bias_kernel<<<ggrid, 256>>>(hs1, w_ihr + (size_t)1 * GATES * HID,
                                     b_ih + 2 * GATES, b_hh + 2 * GATES, pre, HID);
    lstm_kernel<<<BATCH, LTHREADS, LSTM_SMEM_BYTES>>>(pre, w_hh + (size_t)2 * GATES * HID, hs0);

    // Fused attention pooling + MLP head
    attn_mlp_kernel<<<BATCH, 128>>>(hs0, w_attn, b_attn, w1, b1, w2, b2, out);
}